// round 14
// baseline (speedup 1.0000x reference)
#include <cuda_runtime.h>
#include <cuda_fp16.h>
#include <stdint.h>

#define C_DIM 16
#define G_DIM 8192
#define S_DIM 8
#define L_DIM 3
#define B_DIM 32
#define SL    (S_DIM * L_DIM)   // 24

#define G_PER_BLOCK 32
#define THREADS     256
#define N_TILES     (C_DIM * (G_DIM / G_PER_BLOCK))   // 4096

// Rows below THRESH_ROWS are gathered through L1 (footprint 216KB ~ L1D);
// rows above bypass L1 to L2 (no fills). Byte threshold = rows * 64.
#define THRESH_BYTES (3456 * 64)

// xt in fp16: row g = 32 halves = 64B, aligned.
__device__ __align__(128) __half2 g_xh[G_DIM * (B_DIM / 2)];

// ---------------------------------------------------------------------------
// Kernel 1: transpose x (B,G) f32 -> g_xh (G, B/2) half2, no smem.
// ---------------------------------------------------------------------------
__global__ __launch_bounds__(256)
void transpose_x_kernel(const float* __restrict__ x) {
    const int t = blockIdx.x * 256 + threadIdx.x;
    const int g = t >> 3;
    const int q = t & 7;          // b = 4q .. 4q+3

    float f0 = __ldcs(&x[(4 * q + 0) * G_DIM + g]);
    float f1 = __ldcs(&x[(4 * q + 1) * G_DIM + g]);
    float f2 = __ldcs(&x[(4 * q + 2) * G_DIM + g]);
    float f3 = __ldcs(&x[(4 * q + 3) * G_DIM + g]);
    __half2 h0 = __floats2half2_rn(f0, f1);
    __half2 h1 = __floats2half2_rn(f2, f3);

    uint2* dst = (uint2*)&g_xh[g * (B_DIM / 2) + q * 2];
    *dst = make_uint2(*(unsigned*)&h0, *(unsigned*)&h1);
}

// Extract byte offset (idx*64) for index slot k (0..23) from 12 packed words.
__device__ __forceinline__ int idx_off(const unsigned* uw, int k) {
    unsigned w = uw[k >> 1];
    return (k & 1) ? (int)((w >> 13) & 0x7FFF8u)
                   : (int)((w << 3) & 0x7FFF8u);
}

// Gather 8B: L1-cached path for low rows, L1-bypass (.cg, no fill) for high.
// Predicated dual-load: no branch, masked-off lanes emit no wavefronts.
__device__ __forceinline__ uint2 gload(const char* xb, int off) {
    uint2 r;
    const char* p = xb + off;
    asm volatile(
        "{\n\t"
        ".reg .pred p0;\n\t"
        "setp.lt.s32 p0, %2, %3;\n\t"
        "@p0  ld.global.nc.v2.u32 {%0,%1}, [%4];\n\t"
        "@!p0 ld.global.cg.v2.u32 {%0,%1}, [%4];\n\t"
        "}"
        : "=r"(r.x), "=r"(r.y)
        : "r"(off), "n"(THRESH_BYTES), "l"(p));
    return r;
}

// ---------------------------------------------------------------------------
// Kernel 2: block = 256 threads = 8 warps = 32 g (validated core).
// Warp handles 4 g (lane>>3 = sub-g, lane&7 = 8B octet; LDG.64 gathers,
// split across L1/L2 pipes by row threshold). u16-packed indices ->
// 3 LDS.128 -> regs. fp16 pair-accum, fp32 masters. PDL overlap.
// ---------------------------------------------------------------------------
__global__ __launch_bounds__(THREADS, 8)
void clause_body_kernel(const void* __restrict__ Iraw,
                        float* __restrict__ out) {
    __shared__ unsigned short sIdx[G_PER_BLOCK * SL];   // 1.5 KB
    __shared__ float tile[B_DIM][33];                   // 4.2 KB

    const int tid    = threadIdx.x;
    const int lane   = tid & 31;
    const int c      = blockIdx.x >> 8;           // 256 tiles of 32 g per c
    const int g_base = (blockIdx.x & 255) << 5;   // *32

    // Detect int64 vs int32 from I's first 16 high words.
    int hi = 0;
    if (lane < 16) hi = __ldcs(&((const int*)Iraw)[2 * lane + 1]);
    const bool is64 = (__ballot_sync(0xffffffffu, hi != 0) == 0u);

    // Stage 768 indices as u16 = (idx & 8191) << 3, streaming loads.
    const long long base = ((long long)(c * G_DIM + g_base)) * SL;
    if (is64) {
        const long long* Ip = (const long long*)Iraw + base;
#pragma unroll
        for (int k = 0; k < 3; k++) {
            int e = tid + k * THREADS;
            sIdx[e] = (unsigned short)((((int)__ldcs(&Ip[e])) & (G_DIM - 1)) << 3);
        }
    } else {
        const int* Ip = (const int*)Iraw + base;
#pragma unroll
        for (int k = 0; k < 3; k++) {
            int e = tid + k * THREADS;
            sIdx[e] = (unsigned short)((__ldcs(&Ip[e]) & (G_DIM - 1)) << 3);
        }
    }
    __syncthreads();

    const int warp = tid >> 5;
    const int gl   = warp * 4 + (lane >> 3);   // local g (0..31)
    const int oct  = lane & 7;                 // 8B octet -> b = 4*oct..4*oct+3

    const char* xb = (const char*)g_xh + oct * 8;

    // Pull all 24 packed indices for this g: 3 x LDS.128, 12 regs.
    unsigned uw[12];
    {
        const uint4* myI = (const uint4*)&sIdx[gl * SL];
        uint4 w0 = myI[0], w1 = myI[1], w2 = myI[2];
        uw[0] = w0.x; uw[1] = w0.y; uw[2]  = w0.z; uw[3]  = w0.w;
        uw[4] = w1.x; uw[5] = w1.y; uw[6]  = w1.z; uw[7]  = w1.w;
        uw[8] = w2.x; uw[9] = w2.y; uw[10] = w2.z; uw[11] = w2.w;
    }

    // PDL: g_xh must be complete before the first gather.
    cudaGridDependencySynchronize();

    float a0 = 0.f, a1 = 0.f, a2 = 0.f, a3 = 0.f;
#pragma unroll
    for (int j = 0; j < 4; j++) {           // s = 2j, 2j+1
        int k = 6 * j;
        uint2 r0 = gload(xb, idx_off(uw, k + 0));
        uint2 r1 = gload(xb, idx_off(uw, k + 1));
        uint2 r2 = gload(xb, idx_off(uw, k + 2));
        uint2 r3 = gload(xb, idx_off(uw, k + 3));
        uint2 r4 = gload(xb, idx_off(uw, k + 4));
        uint2 r5 = gload(xb, idx_off(uw, k + 5));

        __half2 pa0 = __hmul2(__hmul2(*(__half2*)&r0.x, *(__half2*)&r1.x), *(__half2*)&r2.x);
        __half2 pb0 = __hmul2(__hmul2(*(__half2*)&r0.y, *(__half2*)&r1.y), *(__half2*)&r2.y);
        __half2 pa1 = __hmul2(__hmul2(*(__half2*)&r3.x, *(__half2*)&r4.x), *(__half2*)&r5.x);
        __half2 pb1 = __hmul2(__hmul2(*(__half2*)&r3.y, *(__half2*)&r4.y), *(__half2*)&r5.y);

        __half2 qa = __hadd2(pa0, pa1);     // pair-sum in fp16
        __half2 qb = __hadd2(pb0, pb1);
        float2 fa = __half22float2(qa);
        float2 fb = __half22float2(qb);
        a0 += fa.x; a1 += fa.y;
        a2 += fb.x; a3 += fb.y;
    }

    // tile[b][gl]: bank = 4*oct + gl + i mod 32 -> conflict-free.
    tile[4 * oct + 0][gl] = a0;
    tile[4 * oct + 1][gl] = a1;
    tile[4 * oct + 2][gl] = a2;
    tile[4 * oct + 3][gl] = a3;
    __syncthreads();

    // Writeout: thread -> (b, 4 consecutive g), one streaming STG.128.
    {
        int b  = tid >> 3;          // 0..31
        int q4 = (tid & 7) * 4;     // 0..28
        float4 v = make_float4(tile[b][q4 + 0], tile[b][q4 + 1],
                               tile[b][q4 + 2], tile[b][q4 + 3]);
        __stcs((float4*)&out[((long long)c * B_DIM + b) * G_DIM + g_base + q4], v);
    }
}

extern "C" void kernel_launch(void* const* d_in, const int* in_sizes, int n_in,
                              void* d_out, int out_size) {
    const float* x = nullptr;
    const void*  I = nullptr;
    for (int i = 0; i < n_in; i++) {
        if (in_sizes[i] == B_DIM * G_DIM)            x = (const float*)d_in[i];
        else if (in_sizes[i] == C_DIM * G_DIM * SL)  I = d_in[i];
    }
    float* out = (float*)d_out;

    transpose_x_kernel<<<(G_DIM * 8) / 256, 256>>>(x);

    // Clause kernel with programmatic dependent launch: overlaps its index
    // staging with the transpose.
    cudaLaunchConfig_t cfg = {};
    cfg.gridDim  = dim3(N_TILES);
    cfg.blockDim = dim3(THREADS);
    cfg.dynamicSmemBytes = 0;
    cfg.stream = 0;
    cudaLaunchAttribute attrs[1];
    attrs[0].id = cudaLaunchAttributeProgrammaticStreamSerialization;
    attrs[0].val.programmaticStreamSerializationAllowed = 1;
    cfg.attrs = attrs;
    cfg.numAttrs = 1;
    cudaLaunchKernelEx(&cfg, clause_body_kernel, I, out);
}

// round 15
// speedup vs baseline: 3.2489x; 3.2489x over previous
#include <cuda_runtime.h>
#include <cuda_fp16.h>
#include <stdint.h>

#define C_DIM 16
#define G_DIM 8192
#define S_DIM 8
#define L_DIM 3
#define B_DIM 32
#define SL    (S_DIM * L_DIM)   // 24

#define G_PER_BLOCK 32
#define THREADS     256
#define N_TILES     (C_DIM * (G_DIM / G_PER_BLOCK))   // 4096

// xt in fp16: row g = 32 halves = 64B, aligned. Working set 512KB.
__device__ __align__(128) __half2 g_xh[G_DIM * (B_DIM / 2)];

// ---------------------------------------------------------------------------
// Kernel 1: transpose x (B,G) f32 -> g_xh (G, B/2) half2, no smem.
// ---------------------------------------------------------------------------
__global__ __launch_bounds__(256)
void transpose_x_kernel(const float* __restrict__ x) {
    const int t = blockIdx.x * 256 + threadIdx.x;
    const int g = t >> 3;
    const int q = t & 7;          // b = 4q .. 4q+3

    float f0 = __ldcs(&x[(4 * q + 0) * G_DIM + g]);
    float f1 = __ldcs(&x[(4 * q + 1) * G_DIM + g]);
    float f2 = __ldcs(&x[(4 * q + 2) * G_DIM + g]);
    float f3 = __ldcs(&x[(4 * q + 3) * G_DIM + g]);
    __half2 h0 = __floats2half2_rn(f0, f1);
    __half2 h1 = __floats2half2_rn(f2, f3);

    uint2* dst = (uint2*)&g_xh[g * (B_DIM / 2) + q * 2];
    *dst = make_uint2(*(unsigned*)&h0, *(unsigned*)&h1);
}

// Extract byte offset (idx*64) for index slot k (0..23) from 12 packed words.
__device__ __forceinline__ int idx_off(const unsigned* uw, int k) {
    unsigned w = uw[k >> 1];
    return (k & 1) ? (int)((w >> 13) & 0x7FFF8u)
                   : (int)((w << 3) & 0x7FFF8u);
}

// ---------------------------------------------------------------------------
// Kernel 2: block = 256 threads = 8 warps = 32 g (validated core).
// Warp handles 4 g (lane>>3 = sub-g, lane&7 = 8B octet; LDG.64 gathers).
// NEW: all 24 gathers issued up front via asm volatile (ptxas cannot sink
// them) -> ~24 rows in flight per warp; exposed waits per tile ~1 not 4.
// u16-packed indices -> 3 LDS.128 -> regs. fp16 pair-accum, fp32 masters.
// PDL: staging overlaps the transpose. Grid: 4096 blocks.
// ---------------------------------------------------------------------------
__global__ __launch_bounds__(THREADS)
void clause_body_kernel(const void* __restrict__ Iraw,
                        float* __restrict__ out) {
    __shared__ unsigned short sIdx[G_PER_BLOCK * SL];   // 1.5 KB
    __shared__ float tile[B_DIM][33];                   // 4.2 KB

    const int tid    = threadIdx.x;
    const int lane   = tid & 31;
    const int c      = blockIdx.x >> 8;           // 256 tiles of 32 g per c
    const int g_base = (blockIdx.x & 255) << 5;   // *32

    // Detect int64 vs int32 from I's first 16 high words.
    int hi = 0;
    if (lane < 16) hi = __ldcs(&((const int*)Iraw)[2 * lane + 1]);
    const bool is64 = (__ballot_sync(0xffffffffu, hi != 0) == 0u);

    // Stage 768 indices as u16 = (idx & 8191) << 3, streaming loads.
    const long long base = ((long long)(c * G_DIM + g_base)) * SL;
    if (is64) {
        const long long* Ip = (const long long*)Iraw + base;
#pragma unroll
        for (int k = 0; k < 3; k++) {
            int e = tid + k * THREADS;
            sIdx[e] = (unsigned short)((((int)__ldcs(&Ip[e])) & (G_DIM - 1)) << 3);
        }
    } else {
        const int* Ip = (const int*)Iraw + base;
#pragma unroll
        for (int k = 0; k < 3; k++) {
            int e = tid + k * THREADS;
            sIdx[e] = (unsigned short)((__ldcs(&Ip[e]) & (G_DIM - 1)) << 3);
        }
    }
    __syncthreads();

    const int warp = tid >> 5;
    const int gl   = warp * 4 + (lane >> 3);   // local g (0..31)
    const int oct  = lane & 7;                 // 8B octet -> b = 4*oct..4*oct+3

    const char* xb = (const char*)g_xh + oct * 8;

    // Pull all 24 packed indices for this g: 3 x LDS.128, 12 regs.
    unsigned uw[12];
    {
        const uint4* myI = (const uint4*)&sIdx[gl * SL];
        uint4 w0 = myI[0], w1 = myI[1], w2 = myI[2];
        uw[0] = w0.x; uw[1] = w0.y; uw[2]  = w0.z; uw[3]  = w0.w;
        uw[4] = w1.x; uw[5] = w1.y; uw[6]  = w1.z; uw[7]  = w1.w;
        uw[8] = w2.x; uw[9] = w2.y; uw[10] = w2.z; uw[11] = w2.w;
    }

    // PDL: g_xh must be complete before the first gather.
    cudaGridDependencySynchronize();

    // Issue ALL 24 gathers first (asm volatile keeps them batched up front).
    uint2 r[SL];
#pragma unroll
    for (int m = 0; m < SL; m++) {
        const char* p = xb + idx_off(uw, m);
        asm volatile("ld.global.nc.v2.u32 {%0,%1}, [%2];"
                     : "=r"(r[m].x), "=r"(r[m].y) : "l"(p));
    }

    float a0 = 0.f, a1 = 0.f, a2 = 0.f, a3 = 0.f;
#pragma unroll
    for (int j = 0; j < 4; j++) {           // s = 2j, 2j+1
        const uint2* q = r + 6 * j;
        __half2 pa0 = __hmul2(__hmul2(*(__half2*)&q[0].x, *(__half2*)&q[1].x), *(__half2*)&q[2].x);
        __half2 pb0 = __hmul2(__hmul2(*(__half2*)&q[0].y, *(__half2*)&q[1].y), *(__half2*)&q[2].y);
        __half2 pa1 = __hmul2(__hmul2(*(__half2*)&q[3].x, *(__half2*)&q[4].x), *(__half2*)&q[5].x);
        __half2 pb1 = __hmul2(__hmul2(*(__half2*)&q[3].y, *(__half2*)&q[4].y), *(__half2*)&q[5].y);

        __half2 qa = __hadd2(pa0, pa1);     // pair-sum in fp16
        __half2 qb = __hadd2(pb0, pb1);
        float2 fa = __half22float2(qa);
        float2 fb = __half22float2(qb);
        a0 += fa.x; a1 += fa.y;
        a2 += fb.x; a3 += fb.y;
    }

    // tile[b][gl]: bank = 4*oct + gl + i mod 32 -> conflict-free.
    tile[4 * oct + 0][gl] = a0;
    tile[4 * oct + 1][gl] = a1;
    tile[4 * oct + 2][gl] = a2;
    tile[4 * oct + 3][gl] = a3;
    __syncthreads();

    // Writeout: thread -> (b, 4 consecutive g), one streaming STG.128.
    {
        int b  = tid >> 3;          // 0..31
        int q4 = (tid & 7) * 4;     // 0..28
        float4 v = make_float4(tile[b][q4 + 0], tile[b][q4 + 1],
                               tile[b][q4 + 2], tile[b][q4 + 3]);
        __stcs((float4*)&out[((long long)c * B_DIM + b) * G_DIM + g_base + q4], v);
    }
}

extern "C" void kernel_launch(void* const* d_in, const int* in_sizes, int n_in,
                              void* d_out, int out_size) {
    const float* x = nullptr;
    const void*  I = nullptr;
    for (int i = 0; i < n_in; i++) {
        if (in_sizes[i] == B_DIM * G_DIM)            x = (const float*)d_in[i];
        else if (in_sizes[i] == C_DIM * G_DIM * SL)  I = d_in[i];
    }
    float* out = (float*)d_out;

    transpose_x_kernel<<<(G_DIM * 8) / 256, 256>>>(x);

    // Clause kernel with programmatic dependent launch: overlaps its index
    // staging with the transpose.
    cudaLaunchConfig_t cfg = {};
    cfg.gridDim  = dim3(N_TILES);
    cfg.blockDim = dim3(THREADS);
    cfg.dynamicSmemBytes = 0;
    cfg.stream = 0;
    cudaLaunchAttribute attrs[1];
    attrs[0].id = cudaLaunchAttributeProgrammaticStreamSerialization;
    attrs[0].val.programmaticStreamSerializationAllowed = 1;
    cfg.attrs = attrs;
    cfg.numAttrs = 1;
    cudaLaunchKernelEx(&cfg, clause_body_kernel, I, out);
}